// round 3
// baseline (speedup 1.0000x reference)
#include <cuda_runtime.h>
#include <cstdint>
#include <math.h>

// ---------------------------------------------------------------------------
// SO3Reparameterize fused kernel, round 3.
// Key change vs R1/R2 (both ~100us, everything <35% of peak): NO CTA barriers
// in the main loop. Each warp owns 64 rows and runs its own cp.async ring
// (producer == consumer warp => wait_group + __syncwarp only). Warps drift to
// overlap each other's DRAM stalls with compute.
// Tile layout transposed to [k-pair][row] so one linear conflict-free LDS.128
// fetches both of a thread's rows for a k-pair.
// ---------------------------------------------------------------------------

#define B_ROWS   65536
#define D_IN     1024
#define NBLK     148
#define NWARP    7
#define NTHR     (NWARP * 32)         // 224
#define WROWS    64                   // rows per warp (2 per thread)
#define CHUNK_K  32
#define NCHUNK   (D_IN / CHUNK_K)     // 32
#define NPAIR    (CHUNK_K / 2)        // 16
#define STAGES   3
#define TILE_U64 (NPAIR * WROWS)      // 1024 f32x2 per stage tile
#define TILE_B   (TILE_U64 * 8)       // 8192 B
#define WRING_B  (STAGES * TILE_B)    // 24576 B per warp
#define WP_U64   (512 * 10)           // 512 k-pairs x (9 coeffs + pad) f32x2
#define WP_BYTES (WP_U64 * 8)         // 40960 B
#define SMEM_BYTES (WP_BYTES + NWARP * WRING_B)   // 212992 B (< 227KB)

typedef unsigned long long ull;

__device__ __forceinline__ void fma2(ull &acc, ull x, ull w) {
    asm("fma.rn.f32x2 %0, %1, %2, %0;" : "+l"(acc) : "l"(x), "l"(w));
}
__device__ __forceinline__ ull pack2(float lo, float hi) {
    ull r; asm("mov.b64 %0, {%1, %2};" : "=l"(r) : "f"(lo), "f"(hi)); return r;
}
__device__ __forceinline__ float2 unpack2(ull v) {
    float2 f; asm("mov.b64 {%0, %1}, %2;" : "=f"(f.x), "=f"(f.y) : "l"(v)); return f;
}
__device__ __forceinline__ void cp8(uint32_t dst, const void* src) {
    asm volatile("cp.async.ca.shared.global [%0], [%1], 8;" :: "r"(dst), "l"(src) : "memory");
}
__device__ __forceinline__ void cp_commit() {
    asm volatile("cp.async.commit_group;" ::: "memory");
}
__device__ __forceinline__ void cp_wait1() {
    asm volatile("cp.async.wait_group 1;" ::: "memory");
}

__device__ __forceinline__ float softplus_f(float x) {
    return fmaxf(x, 0.0f) + log1pf(expf(-fabsf(x)));
}

__device__ __forceinline__ void rodrigues(float vx, float vy, float vz, float R[9]) {
    float n2  = vx * vx + vy * vy + vz * vz;
    float th  = sqrtf(n2);
    float inv = 1.0f / th;                 // matches reference (no zero guard)
    float x = vx * inv, y = vy * inv, z = vz * inv;
    float s, c;
    sincosf(th, &s, &c);
    float C = 1.0f - c;
    float xC = x * C, yC = y * C, zC = z * C;
    float xs_ = x * s, ys_ = y * s, zs_ = z * s;
    R[0] = c + x * xC;  R[1] = x * yC - zs_; R[2] = x * zC + ys_;
    R[3] = x * yC + zs_; R[4] = c + y * yC;  R[5] = y * zC - xs_;
    R[6] = x * zC - ys_; R[7] = y * zC + xs_; R[8] = c + z * zC;
}

__device__ __forceinline__ void emit_row(const float y[9], int row,
                                         const float* __restrict__ eps,
                                         const float* __restrict__ bmu,
                                         const float* __restrict__ bd,
                                         const float* __restrict__ bl,
                                         float* __restrict__ out)
{
    float mux = y[0] + __ldg(bmu + 0);
    float muy = y[1] + __ldg(bmu + 1);
    float muz = y[2] + __ldg(bmu + 2);
    float d0 = softplus_f(y[3] + __ldg(bd + 0));
    float d1 = softplus_f(y[4] + __ldg(bd + 1));
    float d2 = softplus_f(y[5] + __ldg(bd + 2));
    float l0 = y[6] + __ldg(bl + 0);
    float l1 = y[7] + __ldg(bl + 1);
    float l2 = y[8] + __ldg(bl + 2);

    float e0 = __ldg(eps + (size_t)row * 3 + 0);
    float e1 = __ldg(eps + (size_t)row * 3 + 1);
    float e2 = __ldg(eps + (size_t)row * 3 + 2);

    float s0 = sqrtf(d0) * e0;
    float s1 = sqrtf(d1) * e1;
    float s2 = sqrtf(d2) * e2;

    float v0 = s0;
    float v1 = l0 * s0 + s1;
    float v2 = l1 * s0 + l2 * s1 + s2;

    float Rm[9], Rv[9];
    rodrigues(mux, muy, muz, Rm);
    rodrigues(v0, v1, v2, Rv);

    float* o = out + (size_t)row * 9;
#pragma unroll
    for (int i = 0; i < 3; ++i) {
#pragma unroll
        for (int j = 0; j < 3; ++j) {
            o[i * 3 + j] = Rm[i * 3 + 0] * Rv[0 * 3 + j]
                         + Rm[i * 3 + 1] * Rv[1 * 3 + j]
                         + Rm[i * 3 + 2] * Rv[2 * 3 + j];
        }
    }
}

__global__ void __launch_bounds__(NTHR, 1)
so3_kernel(const float* __restrict__ x,   const float* __restrict__ eps,
           const float* __restrict__ Wmu, const float* __restrict__ bmu,
           const float* __restrict__ Wd,  const float* __restrict__ bd,
           const float* __restrict__ Wl,  const float* __restrict__ bl,
           float* __restrict__ out)
{
    extern __shared__ unsigned char smem[];
    ull* Wp = (ull*)smem;                         // [512 k-pairs][10] f32x2
    // per-warp rings follow W
    const int t    = threadIdx.x;
    const int w    = t >> 5;
    const int lane = t & 31;
    const int b    = blockIdx.x;
    const int start = (int)(((long long)b * B_ROWS) / NBLK);
    const int end   = (int)(((long long)(b + 1) * B_ROWS) / NBLK);
    const int nrows = end - start;                // 442 or 443 (<= 448)

    ull* ring = (ull*)(smem + WP_BYTES + w * WRING_B);  // [STAGES][NPAIR][WROWS] f32x2
    const uint32_t ring_s = (uint32_t)__cvta_generic_to_shared(ring);

    // ---- staging geometry: lane covers k-pair p of rows rpar, rpar+2, ... (32 rows)
    const int p    = lane & 15;                   // k-pair within chunk
    const int rpar = lane >> 4;                   // row parity (0 or 1)
    // global src base: row (start + 64w + rpar), float offset 2p
    const float* sbase = x + (size_t)(start + w * WROWS + rpar) * D_IN + 2 * p;
    // clamp mask: bit j set if row start+64w+rpar+2j >= B_ROWS (subtract 448 rows)
    unsigned wmask = 0;
#pragma unroll
    for (int j = 0; j < 32; ++j)
        if (start + w * WROWS + rpar + 2 * j >= B_ROWS) wmask |= (1u << j);
    // smem dst base within a tile: (p*WROWS + rpar)*8 bytes, +j*16 per step
    const uint32_t dbase = ring_s + (uint32_t)((p * WROWS + rpar) * 8);

#define STAGE(ch_, slot_)                                                     \
    do {                                                                      \
        const float* gb_ = sbase + (size_t)(ch_) * CHUNK_K;                   \
        uint32_t db_ = dbase + (uint32_t)(slot_) * TILE_B;                    \
        _Pragma("unroll")                                                     \
        for (int j_ = 0; j_ < 32; ++j_) {                                     \
            const float* p_ = gb_ + (size_t)j_ * (2 * D_IN);                  \
            if ((wmask >> j_) & 1) p_ -= (size_t)448 * D_IN;                  \
            cp8(db_ + (uint32_t)(j_ * 16), p_);                               \
        }                                                                     \
    } while (0)

    // ---- prologue: this warp's chunks 0 and 1
    STAGE(0, 0); cp_commit();
    STAGE(1, 1); cp_commit();

    // ---- pack W into smem as k-pair f32x2 (all threads), one-time barrier
    for (int i = t; i < WP_U64; i += NTHR) {
        int pp = i / 10, c = i % 10;
        int k0 = 2 * pp;
        float lo = 0.0f, hi = 0.0f;
        if (c < 3)      { lo = __ldg(Wmu + k0 * 3 + c);       hi = __ldg(Wmu + (k0 + 1) * 3 + c); }
        else if (c < 6) { lo = __ldg(Wd  + k0 * 3 + (c - 3)); hi = __ldg(Wd  + (k0 + 1) * 3 + (c - 3)); }
        else if (c < 9) { lo = __ldg(Wl  + k0 * 3 + (c - 6)); hi = __ldg(Wl  + (k0 + 1) * 3 + (c - 6)); }
        Wp[i] = pack2(lo, hi);
    }
    __syncthreads();     // W visible to all; the ONLY CTA barrier in the kernel

    ull accA[9], accB[9];
#pragma unroll
    for (int c = 0; c < 9; ++c) { accA[c] = 0ull; accB[c] = 0ull; }

    // ---- main loop: per-warp free-running 3-slot ring, no CTA syncs
    int slot_c = 0;                               // slot holding chunk ch
    for (int ch = 0; ch < NCHUNK; ++ch) {
        cp_wait1();                               // own chunk ch landed
        __syncwarp();                             // cross-lane visibility

        const int nc = ch + STAGES - 1;           // prefetch before compute
        if (nc < NCHUNK) {
            const int slot_p = (slot_c + 2 >= STAGES) ? slot_c - 1 : slot_c + 2;
            STAGE(nc, slot_p);
        }
        cp_commit();                              // uniform group arithmetic

        const ull* tile = ring + (size_t)slot_c * TILE_U64;
        const ull* wrow = Wp + (size_t)ch * NPAIR * 10;

#pragma unroll
        for (int q = 0; q < NPAIR; ++q) {
            // one LDS.128 -> rows 2*lane and 2*lane+1, k-pair q (conflict-free linear)
            ulonglong2 xv = *(const ulonglong2*)(tile + q * WROWS + 2 * lane);
            ulonglong2 w01 = *(const ulonglong2*)(wrow + q * 10 + 0);  // broadcast
            ulonglong2 w23 = *(const ulonglong2*)(wrow + q * 10 + 2);
            ulonglong2 w45 = *(const ulonglong2*)(wrow + q * 10 + 4);
            ulonglong2 w67 = *(const ulonglong2*)(wrow + q * 10 + 6);
            ull        w8  = wrow[q * 10 + 8];
            fma2(accA[0], xv.x, w01.x); fma2(accB[0], xv.y, w01.x);
            fma2(accA[1], xv.x, w01.y); fma2(accB[1], xv.y, w01.y);
            fma2(accA[2], xv.x, w23.x); fma2(accB[2], xv.y, w23.x);
            fma2(accA[3], xv.x, w23.y); fma2(accB[3], xv.y, w23.y);
            fma2(accA[4], xv.x, w45.x); fma2(accB[4], xv.y, w45.x);
            fma2(accA[5], xv.x, w45.y); fma2(accB[5], xv.y, w45.y);
            fma2(accA[6], xv.x, w67.x); fma2(accB[6], xv.y, w67.x);
            fma2(accA[7], xv.x, w67.y); fma2(accB[7], xv.y, w67.y);
            fma2(accA[8], xv.x, w8);    fma2(accB[8], xv.y, w8);
        }

        slot_c = (slot_c == STAGES - 1) ? 0 : slot_c + 1;
    }
#undef STAGE

    // ---- epilogue: per-row SO(3) math, no syncs
    const int rA = w * WROWS + 2 * lane;          // local rows of this thread
    if (rA < nrows) {
        float y[9];
#pragma unroll
        for (int c = 0; c < 9; ++c) { float2 f = unpack2(accA[c]); y[c] = f.x + f.y; }
        emit_row(y, start + rA, eps, bmu, bd, bl, out);
    }
    if (rA + 1 < nrows) {
        float y[9];
#pragma unroll
        for (int c = 0; c < 9; ++c) { float2 f = unpack2(accB[c]); y[c] = f.x + f.y; }
        emit_row(y, start + rA + 1, eps, bmu, bd, bl, out);
    }
}

extern "C" void kernel_launch(void* const* d_in, const int* in_sizes, int n_in,
                              void* d_out, int out_size)
{
    const float* x   = (const float*)d_in[0];
    const float* eps = (const float*)d_in[1];
    const float* Wmu = (const float*)d_in[2];
    const float* bmu = (const float*)d_in[3];
    const float* Wd  = (const float*)d_in[4];
    const float* bd  = (const float*)d_in[5];
    const float* Wl  = (const float*)d_in[6];
    const float* bl  = (const float*)d_in[7];

    cudaFuncSetAttribute(so3_kernel, cudaFuncAttributeMaxDynamicSharedMemorySize, SMEM_BYTES);
    so3_kernel<<<NBLK, NTHR, SMEM_BYTES>>>(x, eps, Wmu, bmu, Wd, bd, Wl, bl, (float*)d_out);
}

// round 6
// speedup vs baseline: 1.3983x; 1.3983x over previous
#include <cuda_runtime.h>
#include <cstdint>
#include <math.h>

// ---------------------------------------------------------------------------
// SO3Reparameterize fused kernel, round 6.
// R4/R5 container failures root-caused: unconditional read of staged row
// tb=t+128 (up to 255) exceeded ROWS_CAP=224 and, on slot 3, the dynamic smem
// allocation -> shared-window OOB trap. Fixed by clamping the read row to 223
// (only ever hit by lanes whose result is discarded; emit guard unchanged).
// Design: R1 structure (coalesced [row][k] staging, 4-stage cp.async ring,
// per-chunk CTA barrier) but TWO co-resident CTAs per SM (grid=296, 128 thr,
// 105KB smem each) so the two barrier domains interleave DRAM-wait vs compute.
// ---------------------------------------------------------------------------

#define B_ROWS   65536
#define D_IN     1024
#define NBLK     296
#define NTHR     128
#define ROWS_CAP 224                  // staged rows per CTA (need <= 222)
#define CHUNK_K  16
#define NCHUNK   (D_IN / CHUNK_K)     // 64
#define NPAIR    (CHUNK_K / 2)        // 8
#define ROW_F    18                   // 16 + 2 pad -> conflict-free LDS.64 reads
#define STAGES   4
#define SLOT_F   (ROWS_CAP * ROW_F)   // 4032 floats
#define SLOT_B   (SLOT_F * 4)         // 16128 B
#define WP_U64   (512 * 10)           // 512 k-pairs x (9 coeffs + pad) f32x2
#define WP_BYTES (WP_U64 * 8)         // 40960 B
#define SMEM_BYTES (WP_BYTES + STAGES * SLOT_B)   // 105472 B  (2 per SM: 210944)

typedef unsigned long long ull;

__device__ __forceinline__ void fma2(ull &acc, ull x, ull w) {
    asm("fma.rn.f32x2 %0, %1, %2, %0;" : "+l"(acc) : "l"(x), "l"(w));
}
__device__ __forceinline__ ull pack2(float lo, float hi) {
    ull r; asm("mov.b64 %0, {%1, %2};" : "=l"(r) : "f"(lo), "f"(hi)); return r;
}
__device__ __forceinline__ float2 unpack2(ull v) {
    float2 f; asm("mov.b64 {%0, %1}, %2;" : "=f"(f.x), "=f"(f.y) : "l"(v)); return f;
}
__device__ __forceinline__ void cp8(uint32_t dst, const void* src) {
    asm volatile("cp.async.ca.shared.global [%0], [%1], 8;" :: "r"(dst), "l"(src) : "memory");
}
__device__ __forceinline__ void cp_commit() {
    asm volatile("cp.async.commit_group;" ::: "memory");
}
__device__ __forceinline__ void cp_wait2() {
    asm volatile("cp.async.wait_group 2;" ::: "memory");
}

__device__ __forceinline__ float softplus_f(float x) {
    return fmaxf(x, 0.0f) + log1pf(expf(-fabsf(x)));
}

__device__ __forceinline__ void rodrigues(float vx, float vy, float vz, float R[9]) {
    float n2  = vx * vx + vy * vy + vz * vz;
    float th  = sqrtf(n2);
    float inv = 1.0f / th;                 // matches reference (no zero guard)
    float x = vx * inv, y = vy * inv, z = vz * inv;
    float s, c;
    sincosf(th, &s, &c);
    float C = 1.0f - c;
    float xC = x * C, yC = y * C, zC = z * C;
    float xs_ = x * s, ys_ = y * s, zs_ = z * s;
    R[0] = c + x * xC;  R[1] = x * yC - zs_; R[2] = x * zC + ys_;
    R[3] = x * yC + zs_; R[4] = c + y * yC;  R[5] = y * zC - xs_;
    R[6] = x * zC - ys_; R[7] = y * zC + xs_; R[8] = c + z * zC;
}

__device__ __forceinline__ void emit_row(const float y[9], int row,
                                         const float* __restrict__ eps,
                                         const float* __restrict__ bmu,
                                         const float* __restrict__ bd,
                                         const float* __restrict__ bl,
                                         float* __restrict__ out)
{
    float mux = y[0] + __ldg(bmu + 0);
    float muy = y[1] + __ldg(bmu + 1);
    float muz = y[2] + __ldg(bmu + 2);
    float d0 = softplus_f(y[3] + __ldg(bd + 0));
    float d1 = softplus_f(y[4] + __ldg(bd + 1));
    float d2 = softplus_f(y[5] + __ldg(bd + 2));
    float l0 = y[6] + __ldg(bl + 0);
    float l1 = y[7] + __ldg(bl + 1);
    float l2 = y[8] + __ldg(bl + 2);

    float e0 = __ldg(eps + (size_t)row * 3 + 0);
    float e1 = __ldg(eps + (size_t)row * 3 + 1);
    float e2 = __ldg(eps + (size_t)row * 3 + 2);

    float s0 = sqrtf(d0) * e0;
    float s1 = sqrtf(d1) * e1;
    float s2 = sqrtf(d2) * e2;

    float v0 = s0;
    float v1 = l0 * s0 + s1;
    float v2 = l1 * s0 + l2 * s1 + s2;

    float Rm[9], Rv[9];
    rodrigues(mux, muy, muz, Rm);
    rodrigues(v0, v1, v2, Rv);

    float* o = out + (size_t)row * 9;
#pragma unroll
    for (int i = 0; i < 3; ++i) {
#pragma unroll
        for (int j = 0; j < 3; ++j) {
            o[i * 3 + j] = Rm[i * 3 + 0] * Rv[0 * 3 + j]
                         + Rm[i * 3 + 1] * Rv[1 * 3 + j]
                         + Rm[i * 3 + 2] * Rv[2 * 3 + j];
        }
    }
}

__global__ void __launch_bounds__(NTHR, 2)
so3_kernel(const float* __restrict__ x,   const float* __restrict__ eps,
           const float* __restrict__ Wmu, const float* __restrict__ bmu,
           const float* __restrict__ Wd,  const float* __restrict__ bd,
           const float* __restrict__ Wl,  const float* __restrict__ bl,
           float* __restrict__ out)
{
    extern __shared__ unsigned char smem[];
    ull*   Wp = (ull*)smem;                       // [512 k-pairs][10] f32x2
    float* xs = (float*)(smem + WP_BYTES);        // [STAGES][ROWS_CAP][ROW_F]
    uint32_t xs_s = (uint32_t)__cvta_generic_to_shared(xs);

    const int t = threadIdx.x;
    const int b = blockIdx.x;
    const int start = (int)(((long long)b * B_ROWS) / NBLK);
    const int end   = (int)(((long long)(b + 1) * B_ROWS) / NBLK);
    const int nrows = end - start;                // 221 or 222 (<= 224)

    // ---- staging geometry: thread covers 8B unit `pos` of rows r0 + 16j
    const int pos = t & 7;                        // 8 x 8B = 64 B = one row-chunk
    const int r0  = t >> 3;                       // 0..15
    const float* sbase = x + (size_t)(start + r0) * D_IN + pos * 2;
    unsigned wmask = 0;                           // rows past B_ROWS wrap back 224
#pragma unroll
    for (int j = 0; j < 14; ++j)
        if (start + r0 + 16 * j >= B_ROWS) wmask |= (1u << j);
    const uint32_t sobase = xs_s + (uint32_t)((r0 * ROW_F + pos * 2) * 4);

#define STAGE(nc_, slot_)                                                     \
    do {                                                                      \
        uint32_t sb_ = sobase + (uint32_t)(slot_) * SLOT_B;                   \
        const float* gb_ = sbase + (size_t)(nc_) * CHUNK_K;                   \
        _Pragma("unroll")                                                     \
        for (int j_ = 0; j_ < 14; ++j_) {                                     \
            const float* p_ = gb_ + (size_t)j_ * (16 * D_IN);                 \
            if ((wmask >> j_) & 1) p_ -= (size_t)224 * D_IN;                  \
            cp8(sb_ + j_ * (16 * ROW_F * 4), p_);                             \
        }                                                                     \
    } while (0)

    // ---- prologue: chunks 0..2
    STAGE(0, 0); cp_commit();
    STAGE(1, 1); cp_commit();
    STAGE(2, 2); cp_commit();

    // ---- pack W into smem as k-pair f32x2 (overlaps prologue cp.asyncs)
    for (int i = t; i < WP_U64; i += NTHR) {
        int p = i / 10, c = i % 10;
        int k0 = 2 * p;
        float lo = 0.0f, hi = 0.0f;
        if (c < 3)      { lo = __ldg(Wmu + k0 * 3 + c);       hi = __ldg(Wmu + (k0 + 1) * 3 + c); }
        else if (c < 6) { lo = __ldg(Wd  + k0 * 3 + (c - 3)); hi = __ldg(Wd  + (k0 + 1) * 3 + (c - 3)); }
        else if (c < 9) { lo = __ldg(Wl  + k0 * 3 + (c - 6)); hi = __ldg(Wl  + (k0 + 1) * 3 + (c - 6)); }
        Wp[i] = pack2(lo, hi);
    }

    ull accA[9], accB[9];
#pragma unroll
    for (int c = 0; c < 9; ++c) { accA[c] = 0ull; accB[c] = 0ull; }

    const int ta  = t;                            // row A: 0..127 (always staged+valid)
    const int tb  = t + NTHR;                     // row B: 128..255 (valid iff < nrows)
    const int tbr = (tb < ROWS_CAP) ? tb : (ROWS_CAP - 1);  // CLAMPED read row <= 223
    // (real rows needed are < nrows <= 222, so the clamp only affects lanes
    //  whose accB is discarded by the tb < nrows emit guard)

    // ---- main loop: 64 chunks, 4-stage ring, prefetch-before-compute
    for (int ch = 0; ch < NCHUNK; ++ch) {
        cp_wait2();                               // chunk ch landed
        __syncthreads();                          // visible to all; ch-1 consumed

        const int nc = ch + STAGES - 1;           // prefetch first, compute after
        if (nc < NCHUNK) {
            STAGE(nc, nc & (STAGES - 1));
        }
        cp_commit();                              // uniform group arithmetic

        const int slot = ch & (STAGES - 1);
        const float* pa = xs + slot * SLOT_F + ta * ROW_F;
        const float* pb = xs + slot * SLOT_F + tbr * ROW_F;
        const ull* wrow = Wp + (size_t)ch * NPAIR * 10;

#pragma unroll
        for (int p = 0; p < NPAIR; ++p) {
            ull xa = *(const ull*)(pa + 2 * p);   // LDS.64, conflict-free (stride 9 mod 16)
            ull xb = *(const ull*)(pb + 2 * p);
            ulonglong2 w01 = *(const ulonglong2*)(wrow + p * 10 + 0);  // broadcast LDS.128
            ulonglong2 w23 = *(const ulonglong2*)(wrow + p * 10 + 2);
            ulonglong2 w45 = *(const ulonglong2*)(wrow + p * 10 + 4);
            ulonglong2 w67 = *(const ulonglong2*)(wrow + p * 10 + 6);
            ull        w8  = wrow[p * 10 + 8];
            fma2(accA[0], xa, w01.x); fma2(accB[0], xb, w01.x);
            fma2(accA[1], xa, w01.y); fma2(accB[1], xb, w01.y);
            fma2(accA[2], xa, w23.x); fma2(accB[2], xb, w23.x);
            fma2(accA[3], xa, w23.y); fma2(accB[3], xb, w23.y);
            fma2(accA[4], xa, w45.x); fma2(accB[4], xb, w45.x);
            fma2(accA[5], xa, w45.y); fma2(accB[5], xb, w45.y);
            fma2(accA[6], xa, w67.x); fma2(accB[6], xb, w67.x);
            fma2(accA[7], xa, w67.y); fma2(accB[7], xb, w67.y);
            fma2(accA[8], xa, w8);    fma2(accB[8], xb, w8);
        }
    }
#undef STAGE

    // ---- epilogue: per-row SO(3) math, pure registers
    {
        float y[9];
#pragma unroll
        for (int c = 0; c < 9; ++c) { float2 f = unpack2(accA[c]); y[c] = f.x + f.y; }
        emit_row(y, start + ta, eps, bmu, bd, bl, out);   // ta < 128 <= nrows: valid
    }
    if (tb < nrows) {
        float y[9];
#pragma unroll
        for (int c = 0; c < 9; ++c) { float2 f = unpack2(accB[c]); y[c] = f.x + f.y; }
        emit_row(y, start + tb, eps, bmu, bd, bl, out);
    }
}

extern "C" void kernel_launch(void* const* d_in, const int* in_sizes, int n_in,
                              void* d_out, int out_size)
{
    cudaFuncSetAttribute(so3_kernel, cudaFuncAttributeMaxDynamicSharedMemorySize, SMEM_BYTES);
    const float* x   = (const float*)d_in[0];
    const float* eps = (const float*)d_in[1];
    const float* Wmu = (const float*)d_in[2];
    const float* bmu = (const float*)d_in[3];
    const float* Wd  = (const float*)d_in[4];
    const float* bd  = (const float*)d_in[5];
    const float* Wl  = (const float*)d_in[6];
    const float* bl  = (const float*)d_in[7];

    so3_kernel<<<NBLK, NTHR, SMEM_BYTES>>>(x, eps, Wmu, bmu, Wd, bd, Wl, bl, (float*)d_out);
}